// round 15
// baseline (speedup 1.0000x reference)
#include <cuda_runtime.h>
#include <math.h>
#include <stdint.h>

#define NN 500000
#define FF 128
#define HH 64
#define BB 1024
#define TILE 128
#define XS_STRIDE 132
#define WB_STRIDE 68   // u32 stride for packed bf16 W tiles (conflict-free frag loads)

// ---------------- scratch (no allocations allowed) ----------------
__device__ float  g_e[2][NN];
__device__ float2 g_pair[2][NN];      // (idx-as-float-bits, e) in segment-sorted order
__device__ int    g_count[2][BB];
__device__ int    g_offset[2][BB + 1];
__device__ int    g_cursor[2][BB];
// pre-split W1^T packed bf16x2: [n 0..63][kp 0..63], kp = k/2 (k even in low half)
__device__ uint32_t g_wb_hi[HH * 64];
__device__ uint32_t g_wb_lo[HH * 64];

// ---------------- helpers ----------------
__device__ __forceinline__ uint32_t bf16x2_pack(float up, float lo) {
    uint32_t d;
    asm("cvt.rn.bf16x2.f32 %0, %1, %2;" : "=r"(d) : "f"(up), "f"(lo));
    return d;
}
__device__ __forceinline__ float bf16_lo_as_f32(uint32_t u) { return __uint_as_float(u << 16); }
__device__ __forceinline__ float bf16_hi_as_f32(uint32_t u) { return __uint_as_float(u & 0xFFFF0000u); }

__device__ __forceinline__ float tanh_fast(float v) {
    float e = __expf(2.0f * v);
    return 1.0f - __fdividef(2.0f, e + 1.0f);
}
__device__ __forceinline__ void mma_bf16(float* c, const uint32_t* a, const uint32_t* b) {
    asm volatile(
        "mma.sync.aligned.m16n8k16.row.col.f32.bf16.bf16.f32 "
        "{%0,%1,%2,%3}, {%4,%5,%6,%7}, {%8,%9}, {%0,%1,%2,%3};"
        : "+f"(c[0]), "+f"(c[1]), "+f"(c[2]), "+f"(c[3])
        : "r"(a[0]), "r"(a[1]), "r"(a[2]), "r"(a[3]), "r"(b[0]), "r"(b[1]));
}
__device__ __forceinline__ void split2(float2 q, uint32_t& hi, uint32_t& lo) {
    hi = bf16x2_pack(q.y, q.x);
    float hx = bf16_lo_as_f32(hi);
    float hy = bf16_hi_as_f32(hi);
    lo = bf16x2_pack(q.y - hy, q.x - hx);
}

// ---------------- K0: init ----------------
__global__ void init_kernel(float* __restrict__ out) {
    int i = blockIdx.x * blockDim.x + threadIdx.x;
    if (i < BB * FF) out[i] = 0.0f;
    if (i < 2 * BB) (&g_count[0][0])[i] = 0;
}

// ---------------- K0b: pre-split + pre-pack W1 ----------------
__global__ void prep_w_kernel(const float* __restrict__ W1) {
    int i = blockIdx.x * blockDim.x + threadIdx.x;
    if (i >= HH * 64) return;
    int n  = i >> 6;
    int kp = i & 63;
    float w0 = W1[(2 * kp)     * HH + n];
    float w1 = W1[(2 * kp + 1) * HH + n];
    uint32_t hi = bf16x2_pack(w1, w0);
    float h0 = bf16_lo_as_f32(hi);
    float h1 = bf16_hi_as_f32(hi);
    uint32_t lo = bf16x2_pack(w1 - h1, w0 - h0);
    g_wb_hi[i] = hi;
    g_wb_lo[i] = lo;
}

// ---------------- K1: score kernel — 4 warps x 32 rows, per-warp staging ----------------
// B fragments loaded once per kt feed TWO m16 tiles (halved smem B traffic).
#define SMEM_WORDS (TILE * XS_STRIDE + 2 * (HH * WB_STRIDE) + 64 + 64)

__global__ __launch_bounds__(128) void score_mma_kernel(
    const float* __restrict__ x1, const float* __restrict__ x2,
    const int* __restrict__ bA, const int* __restrict__ bB,
    const float* __restrict__ b1v, const float* __restrict__ W2)
{
    extern __shared__ float sm[];
    float*    xs  = sm;
    uint32_t* swh = (uint32_t*)(xs + TILE * XS_STRIDE);
    uint32_t* swl = swh + HH * WB_STRIDE;
    float*    b1s = (float*)(swl + HH * WB_STRIDE);
    float*    w2s = b1s + 64;

    const int tid  = threadIdx.x;
    const int wid  = tid >> 5;      // 0..3, each warp owns rows [wid*32, wid*32+32)
    const int lane = tid & 31;
    const int g    = lane >> 2;
    const int tq   = lane & 3;
    const int t    = blockIdx.y;
    const float* x = t ? x2 : x1;
    const int* batch = t ? bB : bA;
    const int n0   = blockIdx.x * TILE;
    const int base = wid * 32;

    // stage packed W (hi+lo): 4096 u32 each — the ONLY CTA-wide barrier
    #pragma unroll
    for (int m = 0; m < 32; ++m) {
        int j = tid + 128 * m;
        int n  = j >> 6;
        int kp = j & 63;
        swh[n * WB_STRIDE + kp] = g_wb_hi[j];
        swl[n * WB_STRIDE + kp] = g_wb_lo[j];
    }
    if (tid < HH) { b1s[tid] = b1v[tid]; w2s[tid] = W2[tid]; }
    __syncthreads();

    // per-warp x staging: this warp loads ONLY its own 32 rows (512B coalesced each)
    #pragma unroll
    for (int i = 0; i < 32; ++i) {
        int r = base + i;
        int node = n0 + r;
        float4 v = make_float4(0.f, 0.f, 0.f, 0.f);
        if (node < NN) v = ((const float4*)x)[node * 32 + lane];
        *(float4*)&xs[r * XS_STRIDE + lane * 4] = v;
    }
    __syncwarp();   // warp-local: no waiting on other warps

    // GEMM: warp computes rows [base, base+32) x 64 hidden (bf16x3 compensated)
    float acc[2][8][4];
    #pragma unroll
    for (int m = 0; m < 2; ++m)
        #pragma unroll
        for (int n = 0; n < 8; ++n)
            #pragma unroll
            for (int c = 0; c < 4; ++c) acc[m][n][c] = 0.0f;

    #pragma unroll
    for (int kt = 0; kt < 8; ++kt) {
        const int k0  = kt * 16;
        const int kp0 = kt * 8;

        // B fragments: loaded once, reused for both m-tiles
        uint32_t bh[8][2], bl[8][2];
        #pragma unroll
        for (int n = 0; n < 8; ++n) {
            int row = (n * 8 + g) * WB_STRIDE + kp0 + tq;
            bh[n][0] = swh[row];
            bh[n][1] = swh[row + 4];
            bl[n][0] = swl[row];
            bl[n][1] = swl[row + 4];
        }

        #pragma unroll
        for (int m = 0; m < 2; ++m) {
            const int r = base + m * 16 + g;
            float2 q0 = *(const float2*)&xs[r       * XS_STRIDE + k0 + 2 * tq];
            float2 q1 = *(const float2*)&xs[(r + 8) * XS_STRIDE + k0 + 2 * tq];
            float2 q2 = *(const float2*)&xs[r       * XS_STRIDE + k0 + 2 * tq + 8];
            float2 q3 = *(const float2*)&xs[(r + 8) * XS_STRIDE + k0 + 2 * tq + 8];

            uint32_t ahi[4], alo[4];
            split2(q0, ahi[0], alo[0]);
            split2(q1, ahi[1], alo[1]);
            split2(q2, ahi[2], alo[2]);
            split2(q3, ahi[3], alo[3]);

            #pragma unroll
            for (int n = 0; n < 8; ++n) {
                mma_bf16(acc[m][n], ahi, bh[n]);
                mma_bf16(acc[m][n], ahi, bl[n]);
                mma_bf16(acc[m][n], alo, bh[n]);
            }
        }
    }

    // epilogue: tanh + W2 dot, butterfly over the 4 lanes holding each row
    #pragma unroll
    for (int m = 0; m < 2; ++m) {
        #pragma unroll
        for (int half = 0; half < 2; ++half) {
            float s = 0.0f;
            #pragma unroll
            for (int n = 0; n < 8; ++n) {
                #pragma unroll
                for (int c = 0; c < 2; ++c) {
                    int col = n * 8 + 2 * tq + c;
                    float h = acc[m][n][half * 2 + c] + b1s[col];
                    s = fmaf(tanh_fast(h), w2s[col], s);
                }
            }
            s += __shfl_xor_sync(0xffffffffu, s, 1);
            s += __shfl_xor_sync(0xffffffffu, s, 2);
            if (tq == 0) {
                int node = n0 + base + m * 16 + half * 8 + g;
                if (node < NN) {
                    g_e[t][node] = __expf(s);
                    atomicAdd(&g_count[t][batch[node]], 1);
                }
            }
        }
    }
}

// ---------------- K2: exclusive prefix scan over segments ----------------
__global__ void scan_kernel() {
    __shared__ int ss[BB];
    int tid = threadIdx.x;
    for (int t = 0; t < 2; ++t) {
        int v = g_count[t][tid];
        ss[tid] = v;
        __syncthreads();
        for (int d = 1; d < BB; d <<= 1) {
            int add = (tid >= d) ? ss[tid - d] : 0;
            __syncthreads();
            ss[tid] += add;
            __syncthreads();
        }
        int incl = ss[tid];
        g_offset[t][tid] = incl - v;
        g_cursor[t][tid] = incl - v;
        if (tid == BB - 1) g_offset[t][BB] = incl;
        __syncthreads();
    }
}

// ---------------- K3: scatter (x8 ILP, fused 8B pair store) ----------------
__global__ __launch_bounds__(512) void scatter_kernel(
    const int* __restrict__ bA, const int* __restrict__ bB)
{
    int t = blockIdx.y;
    int i0 = (blockIdx.x * 512 + threadIdx.x) * 8;
    if (i0 >= NN) return;                     // NN % 8 == 0, no partial group
    const int* batch = t ? bB : bA;
    int4   bv0 = *(const int4*)&batch[i0];
    int4   bv1 = *(const int4*)&batch[i0 + 4];
    float4 ev0 = *(const float4*)&g_e[t][i0];
    float4 ev1 = *(const float4*)&g_e[t][i0 + 4];
    int p0 = atomicAdd(&g_cursor[t][bv0.x], 1);
    int p1 = atomicAdd(&g_cursor[t][bv0.y], 1);
    int p2 = atomicAdd(&g_cursor[t][bv0.z], 1);
    int p3 = atomicAdd(&g_cursor[t][bv0.w], 1);
    int p4 = atomicAdd(&g_cursor[t][bv1.x], 1);
    int p5 = atomicAdd(&g_cursor[t][bv1.y], 1);
    int p6 = atomicAdd(&g_cursor[t][bv1.z], 1);
    int p7 = atomicAdd(&g_cursor[t][bv1.w], 1);
    g_pair[t][p0] = make_float2(__int_as_float(i0 + 0), ev0.x);
    g_pair[t][p1] = make_float2(__int_as_float(i0 + 1), ev0.y);
    g_pair[t][p2] = make_float2(__int_as_float(i0 + 2), ev0.z);
    g_pair[t][p3] = make_float2(__int_as_float(i0 + 3), ev0.w);
    g_pair[t][p4] = make_float2(__int_as_float(i0 + 4), ev1.x);
    g_pair[t][p5] = make_float2(__int_as_float(i0 + 5), ev1.y);
    g_pair[t][p6] = make_float2(__int_as_float(i0 + 6), ev1.z);
    g_pair[t][p7] = make_float2(__int_as_float(i0 + 7), ev1.w);
}

// ---------------- K4: per-segment weighted pooling (16 warps, 32 rows in flight) ----------------
__global__ __launch_bounds__(512) void pool_kernel(
    const float* __restrict__ x1, const float* __restrict__ x2,
    float* __restrict__ out)
{
    const int t = blockIdx.y;
    const int b = blockIdx.x;
    const float4* x4 = (const float4*)(t ? x2 : x1);
    const int start = g_offset[t][b];
    const int end   = g_offset[t][b + 1];
    const int w = threadIdx.x >> 5;    // warp 0..15 -> row slot
    const int l = threadIdx.x & 31;    // lane -> feature quad

    float4 acc = make_float4(0.f, 0.f, 0.f, 0.f);
    float  es  = 0.0f;

    #pragma unroll 2
    for (int p = start + w; p < end; p += 16) {
        float2 pr = g_pair[t][p];
        int   n = __float_as_int(pr.x);
        float e = pr.y;
        float4 xv = x4[n * 32 + l];
        acc.x = fmaf(e, xv.x, acc.x);
        acc.y = fmaf(e, xv.y, acc.y);
        acc.z = fmaf(e, xv.z, acc.z);
        acc.w = fmaf(e, xv.w, acc.w);
        es += e;
    }

    __shared__ float sacc[16][FF];
    __shared__ float ses[16];
    *(float4*)&sacc[w][4 * l] = acc;
    if (l == 0) ses[w] = es;
    __syncthreads();

    if (threadIdx.x < FF && end > start) {
        int f = threadIdx.x;
        float tot = 0.0f;
        #pragma unroll
        for (int g2 = 0; g2 < 16; ++g2) tot += sacc[g2][f];
        float s = 0.0f;
        #pragma unroll
        for (int g2 = 0; g2 < 16; ++g2) s += ses[g2];
        atomicAdd(&out[b * FF + f], 0.5f * tot / s);
    }
}

// ---------------- launch ----------------
extern "C" void kernel_launch(void* const* d_in, const int* in_sizes, int n_in,
                              void* d_out, int out_size) {
    const float *x1 = 0, *x2 = 0, *W1 = 0, *b1v = 0, *W2 = 0;
    const int *bt1 = 0, *bt2 = 0;
    for (int k = 0; k < n_in; ++k) {
        long s = in_sizes[k];
        if (s == (long)NN * FF) { if (!x1) x1 = (const float*)d_in[k]; else if (!x2) x2 = (const float*)d_in[k]; }
        else if (s == NN)       { if (!bt1) bt1 = (const int*)d_in[k]; else if (!bt2) bt2 = (const int*)d_in[k]; }
        else if (s == FF * HH)  { W1 = (const float*)d_in[k]; }
        else if (s == HH)       { if (!b1v) b1v = (const float*)d_in[k]; else if (!W2) W2 = (const float*)d_in[k]; }
    }
    float* out = (float*)d_out;

    init_kernel<<<(BB * FF + 255) / 256, 256>>>(out);
    prep_w_kernel<<<(HH * 64 + 255) / 256, 256>>>(W1);

    const int smem_bytes = SMEM_WORDS * (int)sizeof(float);
    cudaFuncSetAttribute(score_mma_kernel, cudaFuncAttributeMaxDynamicSharedMemorySize, smem_bytes);
    dim3 g1((NN + TILE - 1) / TILE, 2);
    score_mma_kernel<<<g1, 128, smem_bytes>>>(x1, x2, bt1, bt2, b1v, W2);

    scan_kernel<<<1, BB>>>();

    dim3 g3((NN / 8 + 511) / 512, 2);
    scatter_kernel<<<g3, 512>>>(bt1, bt2);

    dim3 g4(BB, 2);
    pool_kernel<<<g4, 512>>>(x1, x2, out);
}

// round 16
// speedup vs baseline: 1.0726x; 1.0726x over previous
#include <cuda_runtime.h>
#include <math.h>
#include <stdint.h>

#define NN 500000
#define FF 128
#define HH 64
#define BB 1024
#define TILE 128
#define XA_STRIDE 68     // u32 stride for packed x rows (64 kp + 4 pad)
#define WQ_STRIDE 144    // u32 per hidden col: 36 quads (32 used + 4 pad, pad ≡ 4 mod 8)

// ---------------- scratch (no allocations allowed) ----------------
__device__ float  g_e[2][NN];
__device__ float2 g_pair[2][NN];      // (idx-as-float-bits, e) in segment-sorted order
__device__ int    g_count[2][BB];
__device__ int    g_offset[2][BB + 1];
__device__ int    g_cursor[2][BB];
// W1 pre-packed into LDS.128 quads: per hidden col j: 8 kt x 4 tq quads (bh0,bh1,bl0,bl1)
__device__ uint32_t g_wq[HH * WQ_STRIDE];

// ---------------- helpers ----------------
__device__ __forceinline__ uint32_t bf16x2_pack(float up, float lo) {
    uint32_t d;
    asm("cvt.rn.bf16x2.f32 %0, %1, %2;" : "=r"(d) : "f"(up), "f"(lo));
    return d;
}
__device__ __forceinline__ float bf16_lo_as_f32(uint32_t u) { return __uint_as_float(u << 16); }
__device__ __forceinline__ float bf16_hi_as_f32(uint32_t u) { return __uint_as_float(u & 0xFFFF0000u); }

__device__ __forceinline__ float tanh_fast(float v) {
    float e = __expf(2.0f * v);
    return 1.0f - __fdividef(2.0f, e + 1.0f);
}
__device__ __forceinline__ void mma_bf16(float* c, const uint32_t* a, uint32_t b0, uint32_t b1) {
    asm volatile(
        "mma.sync.aligned.m16n8k16.row.col.f32.bf16.bf16.f32 "
        "{%0,%1,%2,%3}, {%4,%5,%6,%7}, {%8,%9}, {%0,%1,%2,%3};"
        : "+f"(c[0]), "+f"(c[1]), "+f"(c[2]), "+f"(c[3])
        : "r"(a[0]), "r"(a[1]), "r"(a[2]), "r"(a[3]), "r"(b0), "r"(b1));
}
__device__ __forceinline__ void split2(float a, float b, uint32_t& hi, uint32_t& lo) {
    hi = bf16x2_pack(b, a);            // low half = a (even k), high = b (odd k)
    float hx = bf16_lo_as_f32(hi);
    float hy = bf16_hi_as_f32(hi);
    lo = bf16x2_pack(b - hy, a - hx);
}

// ---------------- K0: init ----------------
__global__ void init_kernel(float* __restrict__ out) {
    int i = blockIdx.x * blockDim.x + threadIdx.x;
    if (i < BB * FF) out[i] = 0.0f;
    if (i < 2 * BB) (&g_count[0][0])[i] = 0;
}

// ---------------- K0b: pre-split + pre-pack W1 into LDS.128 quad layout ----------------
// one thread per quad: quad (j, kt, tq) = {bh(kp), bh(kp+4), bl(kp), bl(kp+4)}, kp = kt*8+tq
__global__ void prep_w_kernel(const float* __restrict__ W1) {
    int i = blockIdx.x * blockDim.x + threadIdx.x;
    if (i >= HH * 32) return;          // 64 cols x 32 quads
    int j   = i >> 5;                  // hidden col 0..63
    int rem = i & 31;
    int kt  = rem >> 2;
    int tq  = rem & 3;
    int kp0 = kt * 8 + tq;
    uint32_t h0, l0, h1, l1;
    split2(W1[(2 * kp0)           * HH + j], W1[(2 * kp0 + 1)           * HH + j], h0, l0);
    split2(W1[(2 * (kp0 + 4))     * HH + j], W1[(2 * (kp0 + 4) + 1)     * HH + j], h1, l1);
    uint32_t* q = &g_wq[j * WQ_STRIDE + (kt * 4 + tq) * 4];
    q[0] = h0; q[1] = h1; q[2] = l0; q[3] = l1;
}

// ---------------- K1: score kernel — 8 warps = 4 row-groups x 2 hidden-halves ----------------
// smem u32 words: xah[128][68] + xal[128][68] + wq[64][144] + b1s[64] + w2s[64] + spart[2][128]
#define SMEM_WORDS (2 * TILE * XA_STRIDE + HH * WQ_STRIDE + 64 + 64 + 2 * TILE)

__global__ __launch_bounds__(256) void score_mma_kernel(
    const float* __restrict__ x1, const float* __restrict__ x2,
    const int* __restrict__ bA, const int* __restrict__ bB,
    const float* __restrict__ b1v, const float* __restrict__ W2)
{
    extern __shared__ uint32_t smu[];
    uint32_t* xah  = smu;                          // [128][68]
    uint32_t* xal  = xah + TILE * XA_STRIDE;       // [128][68]
    uint32_t* wq   = xal + TILE * XA_STRIDE;       // [64][144]
    float*    b1s  = (float*)(wq + HH * WQ_STRIDE);
    float*    w2s  = b1s + 64;
    float*    spart = w2s + 64;                    // [2][128]

    const int tid  = threadIdx.x;
    const int wid  = tid >> 5;
    const int lane = tid & 31;
    const int g    = lane >> 2;
    const int tq   = lane & 3;
    const int rg   = wid >> 1;        // row-group 0..3 (32 rows each)
    const int hh   = wid & 1;         // hidden half 0..1 (n-tiles 4hh..4hh+3)
    const int t    = blockIdx.y;
    const float* x = t ? x2 : x1;
    const int* batch = t ? bB : bA;
    const int n0   = blockIdx.x * TILE;

    // stage W quads (plain coalesced copy, layout precomputed) — one CTA barrier
    #pragma unroll
    for (int m = 0; m < 36; ++m) {
        int j = tid + 256 * m;        // 36*256 = 9216 = HH*WQ_STRIDE
        wq[j] = g_wq[j];
    }
    if (tid < HH) { b1s[tid] = b1v[tid]; w2s[tid] = W2[tid]; }
    __syncthreads();

    // A staging: warp stages 16 rows (its half of the row-group), split hi/lo packed
    {
        int r0 = rg * 32 + hh * 16;
        #pragma unroll
        for (int i = 0; i < 16; ++i) {
            int r = r0 + i;
            int node = n0 + r;
            float4 v = make_float4(0.f, 0.f, 0.f, 0.f);
            if (node < NN) v = ((const float4*)x)[node * 32 + lane];
            uint32_t h0, l0, h1, l1;
            split2(v.x, v.y, h0, l0);
            split2(v.z, v.w, h1, l1);
            *(uint2*)&xah[r * XA_STRIDE + 2 * lane] = make_uint2(h0, h1);
            *(uint2*)&xal[r * XA_STRIDE + 2 * lane] = make_uint2(l0, l1);
        }
    }
    asm volatile("bar.sync %0, 64;" :: "r"(1 + rg) : "memory");   // 2 warps of this row-group

    // GEMM: warp computes rows [rg*32, rg*32+32) x hidden [hh*32, hh*32+32)
    float acc[2][4][4];
    #pragma unroll
    for (int m = 0; m < 2; ++m)
        #pragma unroll
        for (int n = 0; n < 4; ++n)
            #pragma unroll
            for (int c = 0; c < 4; ++c) acc[m][n][c] = 0.0f;

    #pragma unroll
    for (int kt = 0; kt < 8; ++kt) {
        const int kp0 = kt * 8;

        uint4 bq[4];
        #pragma unroll
        for (int nl = 0; nl < 4; ++nl) {
            int j = (hh * 4 + nl) * 8 + g;
            bq[nl] = *(const uint4*)&wq[j * WQ_STRIDE + (kt * 4 + tq) * 4];
        }

        #pragma unroll
        for (int m = 0; m < 2; ++m) {
            const int r = rg * 32 + m * 16 + g;
            uint32_t ahi[4], alo[4];
            ahi[0] = xah[r       * XA_STRIDE + kp0 + tq];
            ahi[1] = xah[(r + 8) * XA_STRIDE + kp0 + tq];
            ahi[2] = xah[r       * XA_STRIDE + kp0 + tq + 4];
            ahi[3] = xah[(r + 8) * XA_STRIDE + kp0 + tq + 4];
            alo[0] = xal[r       * XA_STRIDE + kp0 + tq];
            alo[1] = xal[(r + 8) * XA_STRIDE + kp0 + tq];
            alo[2] = xal[r       * XA_STRIDE + kp0 + tq + 4];
            alo[3] = xal[(r + 8) * XA_STRIDE + kp0 + tq + 4];

            #pragma unroll
            for (int nl = 0; nl < 4; ++nl) {
                mma_bf16(acc[m][nl], ahi, bq[nl].x, bq[nl].y);   // ahi * bhi
                mma_bf16(acc[m][nl], ahi, bq[nl].z, bq[nl].w);   // ahi * blo
                mma_bf16(acc[m][nl], alo, bq[nl].x, bq[nl].y);   // alo * bhi
            }
        }
    }

    // epilogue: partial score over this warp's 32 hidden, butterfly over tq lanes
    #pragma unroll
    for (int m = 0; m < 2; ++m) {
        #pragma unroll
        for (int half = 0; half < 2; ++half) {
            float s = 0.0f;
            #pragma unroll
            for (int nl = 0; nl < 4; ++nl) {
                #pragma unroll
                for (int c = 0; c < 2; ++c) {
                    int col = (hh * 4 + nl) * 8 + 2 * tq + c;
                    float h = acc[m][nl][half * 2 + c] + b1s[col];
                    s = fmaf(tanh_fast(h), w2s[col], s);
                }
            }
            s += __shfl_xor_sync(0xffffffffu, s, 1);
            s += __shfl_xor_sync(0xffffffffu, s, 2);
            if (tq == 0) {
                int row = rg * 32 + m * 16 + half * 8 + g;
                spart[hh * TILE + row] = s;
            }
        }
    }
    asm volatile("bar.sync %0, 64;" :: "r"(1 + rg) : "memory");

    // hh==0 warp finalizes its row-group's 32 rows
    if (hh == 0) {
        int row = rg * 32 + lane;
        int node = n0 + row;
        if (node < NN) {
            float s = spart[row] + spart[TILE + row];
            g_e[t][node] = __expf(s);
            atomicAdd(&g_count[t][batch[node]], 1);
        }
    }
}

// ---------------- K2: exclusive prefix scan over segments ----------------
__global__ void scan_kernel() {
    __shared__ int ss[BB];
    int tid = threadIdx.x;
    for (int t = 0; t < 2; ++t) {
        int v = g_count[t][tid];
        ss[tid] = v;
        __syncthreads();
        for (int d = 1; d < BB; d <<= 1) {
            int add = (tid >= d) ? ss[tid - d] : 0;
            __syncthreads();
            ss[tid] += add;
            __syncthreads();
        }
        int incl = ss[tid];
        g_offset[t][tid] = incl - v;
        g_cursor[t][tid] = incl - v;
        if (tid == BB - 1) g_offset[t][BB] = incl;
        __syncthreads();
    }
}

// ---------------- K3: scatter (x8 ILP, fused 8B pair store) ----------------
__global__ __launch_bounds__(512) void scatter_kernel(
    const int* __restrict__ bA, const int* __restrict__ bB)
{
    int t = blockIdx.y;
    int i0 = (blockIdx.x * 512 + threadIdx.x) * 8;
    if (i0 >= NN) return;                     // NN % 8 == 0, no partial group
    const int* batch = t ? bB : bA;
    int4   bv0 = *(const int4*)&batch[i0];
    int4   bv1 = *(const int4*)&batch[i0 + 4];
    float4 ev0 = *(const float4*)&g_e[t][i0];
    float4 ev1 = *(const float4*)&g_e[t][i0 + 4];
    int p0 = atomicAdd(&g_cursor[t][bv0.x], 1);
    int p1 = atomicAdd(&g_cursor[t][bv0.y], 1);
    int p2 = atomicAdd(&g_cursor[t][bv0.z], 1);
    int p3 = atomicAdd(&g_cursor[t][bv0.w], 1);
    int p4 = atomicAdd(&g_cursor[t][bv1.x], 1);
    int p5 = atomicAdd(&g_cursor[t][bv1.y], 1);
    int p6 = atomicAdd(&g_cursor[t][bv1.z], 1);
    int p7 = atomicAdd(&g_cursor[t][bv1.w], 1);
    g_pair[t][p0] = make_float2(__int_as_float(i0 + 0), ev0.x);
    g_pair[t][p1] = make_float2(__int_as_float(i0 + 1), ev0.y);
    g_pair[t][p2] = make_float2(__int_as_float(i0 + 2), ev0.z);
    g_pair[t][p3] = make_float2(__int_as_float(i0 + 3), ev0.w);
    g_pair[t][p4] = make_float2(__int_as_float(i0 + 4), ev1.x);
    g_pair[t][p5] = make_float2(__int_as_float(i0 + 5), ev1.y);
    g_pair[t][p6] = make_float2(__int_as_float(i0 + 6), ev1.z);
    g_pair[t][p7] = make_float2(__int_as_float(i0 + 7), ev1.w);
}

// ---------------- K4: per-segment weighted pooling (16 warps, 32 rows in flight) ----------------
__global__ __launch_bounds__(512) void pool_kernel(
    const float* __restrict__ x1, const float* __restrict__ x2,
    float* __restrict__ out)
{
    const int t = blockIdx.y;
    const int b = blockIdx.x;
    const float4* x4 = (const float4*)(t ? x2 : x1);
    const int start = g_offset[t][b];
    const int end   = g_offset[t][b + 1];
    const int w = threadIdx.x >> 5;    // warp 0..15 -> row slot
    const int l = threadIdx.x & 31;    // lane -> feature quad

    float4 acc = make_float4(0.f, 0.f, 0.f, 0.f);
    float  es  = 0.0f;

    #pragma unroll 2
    for (int p = start + w; p < end; p += 16) {
        float2 pr = g_pair[t][p];
        int   n = __float_as_int(pr.x);
        float e = pr.y;
        float4 xv = x4[n * 32 + l];
        acc.x = fmaf(e, xv.x, acc.x);
        acc.y = fmaf(e, xv.y, acc.y);
        acc.z = fmaf(e, xv.z, acc.z);
        acc.w = fmaf(e, xv.w, acc.w);
        es += e;
    }

    __shared__ float sacc[16][FF];
    __shared__ float ses[16];
    *(float4*)&sacc[w][4 * l] = acc;
    if (l == 0) ses[w] = es;
    __syncthreads();

    if (threadIdx.x < FF && end > start) {
        int f = threadIdx.x;
        float tot = 0.0f;
        #pragma unroll
        for (int g2 = 0; g2 < 16; ++g2) tot += sacc[g2][f];
        float s = 0.0f;
        #pragma unroll
        for (int g2 = 0; g2 < 16; ++g2) s += ses[g2];
        atomicAdd(&out[b * FF + f], 0.5f * tot / s);
    }
}

// ---------------- launch ----------------
extern "C" void kernel_launch(void* const* d_in, const int* in_sizes, int n_in,
                              void* d_out, int out_size) {
    const float *x1 = 0, *x2 = 0, *W1 = 0, *b1v = 0, *W2 = 0;
    const int *bt1 = 0, *bt2 = 0;
    for (int k = 0; k < n_in; ++k) {
        long s = in_sizes[k];
        if (s == (long)NN * FF) { if (!x1) x1 = (const float*)d_in[k]; else if (!x2) x2 = (const float*)d_in[k]; }
        else if (s == NN)       { if (!bt1) bt1 = (const int*)d_in[k]; else if (!bt2) bt2 = (const int*)d_in[k]; }
        else if (s == FF * HH)  { W1 = (const float*)d_in[k]; }
        else if (s == HH)       { if (!b1v) b1v = (const float*)d_in[k]; else if (!W2) W2 = (const float*)d_in[k]; }
    }
    float* out = (float*)d_out;

    init_kernel<<<(BB * FF + 255) / 256, 256>>>(out);
    prep_w_kernel<<<(HH * 32 + 255) / 256, 256>>>(W1);

    const int smem_bytes = SMEM_WORDS * (int)sizeof(uint32_t);
    cudaFuncSetAttribute(score_mma_kernel, cudaFuncAttributeMaxDynamicSharedMemorySize, smem_bytes);
    dim3 g1((NN + TILE - 1) / TILE, 2);
    score_mma_kernel<<<g1, 256, smem_bytes>>>(x1, x2, bt1, bt2, b1v, W2);

    scan_kernel<<<1, BB>>>();

    dim3 g3((NN / 8 + 511) / 512, 2);
    scatter_kernel<<<g3, 512>>>(bt1, bt2);

    dim3 g4(BB, 2);
    pool_kernel<<<g4, 512>>>(x1, x2, out);
}

// round 17
// speedup vs baseline: 1.1172x; 1.0416x over previous
#include <cuda_runtime.h>
#include <math.h>
#include <stdint.h>

#define NN 500000
#define FF 128
#define HH 64
#define BB 1024
#define TILE 128
#define XA_STRIDE 68     // u32 stride for packed x rows (64 kp + 4 pad)

// ---------------- scratch (no allocations allowed) ----------------
__device__ float  g_e[2][NN];
__device__ float2 g_pair[2][NN];      // (idx-as-float-bits, e) in segment-sorted order
__device__ int    g_count[2][BB];
__device__ int    g_offset[2][BB + 1];
__device__ int    g_cursor[2][BB];
// W1 pre-packed quads, TIGHT layout (L1-resident, read directly by GEMM):
// per hidden col j (0..63): 32 quads (kt*4+tq) of {bh0,bh1,bl0,bl1}
__device__ uint32_t g_wq[HH * 128];

// ---------------- helpers ----------------
__device__ __forceinline__ uint32_t bf16x2_pack(float up, float lo) {
    uint32_t d;
    asm("cvt.rn.bf16x2.f32 %0, %1, %2;" : "=r"(d) : "f"(up), "f"(lo));
    return d;
}
__device__ __forceinline__ float bf16_lo_as_f32(uint32_t u) { return __uint_as_float(u << 16); }
__device__ __forceinline__ float bf16_hi_as_f32(uint32_t u) { return __uint_as_float(u & 0xFFFF0000u); }

__device__ __forceinline__ float tanh_fast(float v) {
    float e = __expf(2.0f * v);
    return 1.0f - __fdividef(2.0f, e + 1.0f);
}
__device__ __forceinline__ void mma_bf16(float* c, const uint32_t* a, uint32_t b0, uint32_t b1) {
    asm volatile(
        "mma.sync.aligned.m16n8k16.row.col.f32.bf16.bf16.f32 "
        "{%0,%1,%2,%3}, {%4,%5,%6,%7}, {%8,%9}, {%0,%1,%2,%3};"
        : "+f"(c[0]), "+f"(c[1]), "+f"(c[2]), "+f"(c[3])
        : "r"(a[0]), "r"(a[1]), "r"(a[2]), "r"(a[3]), "r"(b0), "r"(b1));
}
__device__ __forceinline__ void split2(float a, float b, uint32_t& hi, uint32_t& lo) {
    hi = bf16x2_pack(b, a);            // low half = a (even k), high = b (odd k)
    float hx = bf16_lo_as_f32(hi);
    float hy = bf16_hi_as_f32(hi);
    lo = bf16x2_pack(b - hy, a - hx);
}

// ---------------- K0: init ----------------
__global__ void init_kernel(float* __restrict__ out) {
    int i = blockIdx.x * blockDim.x + threadIdx.x;
    if (i < BB * FF) out[i] = 0.0f;
    if (i < 2 * BB) (&g_count[0][0])[i] = 0;
}

// ---------------- K0b: pre-split + pre-pack W1 into tight quad layout ----------------
__global__ void prep_w_kernel(const float* __restrict__ W1) {
    int i = blockIdx.x * blockDim.x + threadIdx.x;
    if (i >= HH * 32) return;          // 64 cols x 32 quads
    int j   = i >> 5;                  // hidden col 0..63
    int rem = i & 31;
    int kt  = rem >> 2;
    int tq  = rem & 3;
    int kp0 = kt * 8 + tq;
    uint32_t h0, l0, h1, l1;
    split2(W1[(2 * kp0)           * HH + j], W1[(2 * kp0 + 1)           * HH + j], h0, l0);
    split2(W1[(2 * (kp0 + 4))     * HH + j], W1[(2 * (kp0 + 4) + 1)     * HH + j], h1, l1);
    uint32_t* q = &g_wq[j * 128 + (kt * 4 + tq) * 4];
    q[0] = h0; q[1] = h1; q[2] = l0; q[3] = l1;
}

// ---------------- K1: score kernel — B from L1-resident global; NO CTA barrier ----------------
// smem u32: xah[128][68] + xal[128][68] + spart[2][128] + pad (cap occupancy at 2 CTAs/SM
// so L1D keeps >= 70KB and the 37KB W-quad table stays L1-resident)
#define SMEM_WORDS (2 * TILE * XA_STRIDE + 2 * TILE + 1840)

__global__ __launch_bounds__(256) void score_mma_kernel(
    const float* __restrict__ x1, const float* __restrict__ x2,
    const int* __restrict__ bA, const int* __restrict__ bB,
    const float* __restrict__ b1v, const float* __restrict__ W2)
{
    extern __shared__ uint32_t smu[];
    uint32_t* xah   = smu;                          // [128][68]
    uint32_t* xal   = xah + TILE * XA_STRIDE;       // [128][68]
    float*    spart = (float*)(xal + TILE * XA_STRIDE);   // [2][128]

    const int tid  = threadIdx.x;
    const int wid  = tid >> 5;
    const int lane = tid & 31;
    const int g    = lane >> 2;
    const int tq   = lane & 3;
    const int rg   = wid >> 1;        // row-group 0..3 (32 rows each)
    const int hh   = wid & 1;         // hidden half 0..1
    const int t    = blockIdx.y;
    const float* x = t ? x2 : x1;
    const int* batch = t ? bB : bA;
    const int n0   = blockIdx.x * TILE;

    // A staging: warp stages its 16 rows (half of the row-group), split hi/lo packed
    {
        int r0 = rg * 32 + hh * 16;
        #pragma unroll
        for (int i = 0; i < 16; ++i) {
            int r = r0 + i;
            int node = n0 + r;
            float4 v = make_float4(0.f, 0.f, 0.f, 0.f);
            if (node < NN) v = ((const float4*)x)[node * 32 + lane];
            uint32_t h0, l0, h1, l1;
            split2(v.x, v.y, h0, l0);
            split2(v.z, v.w, h1, l1);
            *(uint2*)&xah[r * XA_STRIDE + 2 * lane] = make_uint2(h0, h1);
            *(uint2*)&xal[r * XA_STRIDE + 2 * lane] = make_uint2(l0, l1);
        }
    }
    asm volatile("bar.sync %0, 64;" :: "r"(1 + rg) : "memory");   // 2 warps of this row-group

    // GEMM: warp computes rows [rg*32, rg*32+32) x hidden [hh*32, hh*32+32)
    const uint4* __restrict__ wqg = (const uint4*)g_wq;   // L1-resident after first touch
    float acc[2][4][4];
    #pragma unroll
    for (int m = 0; m < 2; ++m)
        #pragma unroll
        for (int n = 0; n < 4; ++n)
            #pragma unroll
            for (int c = 0; c < 4; ++c) acc[m][n][c] = 0.0f;

    #pragma unroll
    for (int kt = 0; kt < 8; ++kt) {
        const int kp0 = kt * 8;

        uint4 bq[4];
        #pragma unroll
        for (int nl = 0; nl < 4; ++nl) {
            int j = (hh * 4 + nl) * 8 + g;
            bq[nl] = __ldg(&wqg[j * 32 + kt * 4 + tq]);
        }

        #pragma unroll
        for (int m = 0; m < 2; ++m) {
            const int r = rg * 32 + m * 16 + g;
            uint32_t ahi[4], alo[4];
            ahi[0] = xah[r       * XA_STRIDE + kp0 + tq];
            ahi[1] = xah[(r + 8) * XA_STRIDE + kp0 + tq];
            ahi[2] = xah[r       * XA_STRIDE + kp0 + tq + 4];
            ahi[3] = xah[(r + 8) * XA_STRIDE + kp0 + tq + 4];
            alo[0] = xal[r       * XA_STRIDE + kp0 + tq];
            alo[1] = xal[(r + 8) * XA_STRIDE + kp0 + tq];
            alo[2] = xal[r       * XA_STRIDE + kp0 + tq + 4];
            alo[3] = xal[(r + 8) * XA_STRIDE + kp0 + tq + 4];

            #pragma unroll
            for (int nl = 0; nl < 4; ++nl) {
                mma_bf16(acc[m][nl], ahi, bq[nl].x, bq[nl].y);   // ahi * bhi
                mma_bf16(acc[m][nl], ahi, bq[nl].z, bq[nl].w);   // ahi * blo
                mma_bf16(acc[m][nl], alo, bq[nl].x, bq[nl].y);   // alo * bhi
            }
        }
    }

    // b1/W2 for this thread's 8 columns (L1 hits)
    float b1r[8], w2r[8];
    #pragma unroll
    for (int nl = 0; nl < 4; ++nl) {
        #pragma unroll
        for (int c = 0; c < 2; ++c) {
            int col = (hh * 4 + nl) * 8 + 2 * tq + c;
            b1r[nl * 2 + c] = __ldg(&b1v[col]);
            w2r[nl * 2 + c] = __ldg(&W2[col]);
        }
    }

    // epilogue: partial score over this warp's 32 hidden, butterfly over tq lanes
    #pragma unroll
    for (int m = 0; m < 2; ++m) {
        #pragma unroll
        for (int half = 0; half < 2; ++half) {
            float s = 0.0f;
            #pragma unroll
            for (int nl = 0; nl < 4; ++nl) {
                #pragma unroll
                for (int c = 0; c < 2; ++c) {
                    float h = acc[m][nl][half * 2 + c] + b1r[nl * 2 + c];
                    s = fmaf(tanh_fast(h), w2r[nl * 2 + c], s);
                }
            }
            s += __shfl_xor_sync(0xffffffffu, s, 1);
            s += __shfl_xor_sync(0xffffffffu, s, 2);
            if (tq == 0) {
                int row = rg * 32 + m * 16 + half * 8 + g;
                spart[hh * TILE + row] = s;
            }
        }
    }
    asm volatile("bar.sync %0, 64;" :: "r"(1 + rg) : "memory");

    // hh==0 warp finalizes its row-group's 32 rows
    if (hh == 0) {
        int row = rg * 32 + lane;
        int node = n0 + row;
        if (node < NN) {
            float s = spart[row] + spart[TILE + row];
            g_e[t][node] = __expf(s);
            atomicAdd(&g_count[t][batch[node]], 1);
        }
    }
}

// ---------------- K2: exclusive prefix scan over segments ----------------
__global__ void scan_kernel() {
    __shared__ int ss[BB];
    int tid = threadIdx.x;
    for (int t = 0; t < 2; ++t) {
        int v = g_count[t][tid];
        ss[tid] = v;
        __syncthreads();
        for (int d = 1; d < BB; d <<= 1) {
            int add = (tid >= d) ? ss[tid - d] : 0;
            __syncthreads();
            ss[tid] += add;
            __syncthreads();
        }
        int incl = ss[tid];
        g_offset[t][tid] = incl - v;
        g_cursor[t][tid] = incl - v;
        if (tid == BB - 1) g_offset[t][BB] = incl;
        __syncthreads();
    }
}

// ---------------- K3: scatter (x8 ILP, fused 8B pair store) ----------------
__global__ __launch_bounds__(512) void scatter_kernel(
    const int* __restrict__ bA, const int* __restrict__ bB)
{
    int t = blockIdx.y;
    int i0 = (blockIdx.x * 512 + threadIdx.x) * 8;
    if (i0 >= NN) return;                     // NN % 8 == 0, no partial group
    const int* batch = t ? bB : bA;
    int4   bv0 = *(const int4*)&batch[i0];
    int4   bv1 = *(const int4*)&batch[i0 + 4];
    float4 ev0 = *(const float4*)&g_e[t][i0];
    float4 ev1 = *(const float4*)&g_e[t][i0 + 4];
    int p0 = atomicAdd(&g_cursor[t][bv0.x], 1);
    int p1 = atomicAdd(&g_cursor[t][bv0.y], 1);
    int p2 = atomicAdd(&g_cursor[t][bv0.z], 1);
    int p3 = atomicAdd(&g_cursor[t][bv0.w], 1);
    int p4 = atomicAdd(&g_cursor[t][bv1.x], 1);
    int p5 = atomicAdd(&g_cursor[t][bv1.y], 1);
    int p6 = atomicAdd(&g_cursor[t][bv1.z], 1);
    int p7 = atomicAdd(&g_cursor[t][bv1.w], 1);
    g_pair[t][p0] = make_float2(__int_as_float(i0 + 0), ev0.x);
    g_pair[t][p1] = make_float2(__int_as_float(i0 + 1), ev0.y);
    g_pair[t][p2] = make_float2(__int_as_float(i0 + 2), ev0.z);
    g_pair[t][p3] = make_float2(__int_as_float(i0 + 3), ev0.w);
    g_pair[t][p4] = make_float2(__int_as_float(i0 + 4), ev1.x);
    g_pair[t][p5] = make_float2(__int_as_float(i0 + 5), ev1.y);
    g_pair[t][p6] = make_float2(__int_as_float(i0 + 6), ev1.z);
    g_pair[t][p7] = make_float2(__int_as_float(i0 + 7), ev1.w);
}

// ---------------- K4: per-segment weighted pooling (16 warps, 32 rows in flight) ----------------
__global__ __launch_bounds__(512) void pool_kernel(
    const float* __restrict__ x1, const float* __restrict__ x2,
    float* __restrict__ out)
{
    const int t = blockIdx.y;
    const int b = blockIdx.x;
    const float4* x4 = (const float4*)(t ? x2 : x1);
    const int start = g_offset[t][b];
    const int end   = g_offset[t][b + 1];
    const int w = threadIdx.x >> 5;    // warp 0..15 -> row slot
    const int l = threadIdx.x & 31;    // lane -> feature quad

    float4 acc = make_float4(0.f, 0.f, 0.f, 0.f);
    float  es  = 0.0f;

    #pragma unroll 2
    for (int p = start + w; p < end; p += 16) {
        float2 pr = g_pair[t][p];
        int   n = __float_as_int(pr.x);
        float e = pr.y;
        float4 xv = x4[n * 32 + l];
        acc.x = fmaf(e, xv.x, acc.x);
        acc.y = fmaf(e, xv.y, acc.y);
        acc.z = fmaf(e, xv.z, acc.z);
        acc.w = fmaf(e, xv.w, acc.w);
        es += e;
    }

    __shared__ float sacc[16][FF];
    __shared__ float ses[16];
    *(float4*)&sacc[w][4 * l] = acc;
    if (l == 0) ses[w] = es;
    __syncthreads();

    if (threadIdx.x < FF && end > start) {
        int f = threadIdx.x;
        float tot = 0.0f;
        #pragma unroll
        for (int g2 = 0; g2 < 16; ++g2) tot += sacc[g2][f];
        float s = 0.0f;
        #pragma unroll
        for (int g2 = 0; g2 < 16; ++g2) s += ses[g2];
        atomicAdd(&out[b * FF + f], 0.5f * tot / s);
    }
}

// ---------------- launch ----------------
extern "C" void kernel_launch(void* const* d_in, const int* in_sizes, int n_in,
                              void* d_out, int out_size) {
    const float *x1 = 0, *x2 = 0, *W1 = 0, *b1v = 0, *W2 = 0;
    const int *bt1 = 0, *bt2 = 0;
    for (int k = 0; k < n_in; ++k) {
        long s = in_sizes[k];
        if (s == (long)NN * FF) { if (!x1) x1 = (const float*)d_in[k]; else if (!x2) x2 = (const float*)d_in[k]; }
        else if (s == NN)       { if (!bt1) bt1 = (const int*)d_in[k]; else if (!bt2) bt2 = (const int*)d_in[k]; }
        else if (s == FF * HH)  { W1 = (const float*)d_in[k]; }
        else if (s == HH)       { if (!b1v) b1v = (const float*)d_in[k]; else if (!W2) W2 = (const float*)d_in[k]; }
    }
    float* out = (float*)d_out;

    init_kernel<<<(BB * FF + 255) / 256, 256>>>(out);
    prep_w_kernel<<<(HH * 32 + 255) / 256, 256>>>(W1);

    const int smem_bytes = SMEM_WORDS * (int)sizeof(uint32_t);
    cudaFuncSetAttribute(score_mma_kernel, cudaFuncAttributeMaxDynamicSharedMemorySize, smem_bytes);
    dim3 g1((NN + TILE - 1) / TILE, 2);
    score_mma_kernel<<<g1, 256, smem_bytes>>>(x1, x2, bt1, bt2, b1v, W2);

    scan_kernel<<<1, BB>>>();

    dim3 g3((NN / 8 + 511) / 512, 2);
    scatter_kernel<<<g3, 512>>>(bt1, bt2);

    dim3 g4(BB, 2);
    pool_kernel<<<g4, 512>>>(x1, x2, out);
}